// round 4
// baseline (speedup 1.0000x reference)
#include <cuda_runtime.h>

#define D 64
#define MAX_NODES 50000
#define MAX_EDGES 800000
#define SCAN_BLK 1024
#define NB_SCAN ((MAX_NODES + SCAN_BLK - 1) / SCAN_BLK)   // 49

// ---- scratch ----
__device__ float    g_support[MAX_NODES * D];   // X @ W
__device__ int      g_deg[MAX_NODES];
__device__ int      g_offsets[MAX_NODES];       // exclusive prefix of deg
__device__ int      g_cursor[MAX_NODES];        // fill cursors; == row end after fill
__device__ unsigned g_scanstate[NB_SCAN];       // bit31=prefix, bit30=aggregate, [0:24)=value
__device__ int2     g_edges[MAX_EDGES];         // (src, bitcast(w)) bucketed by dst

// ---------------------------------------------------------------------------
__global__ void zero_kernel(int n_nodes) {
    int i = blockIdx.x * blockDim.x + threadIdx.x;
    if (i < n_nodes) g_deg[i] = 0;
    if (i < NB_SCAN) g_scanstate[i] = 0u;
}

__global__ void count_kernel(const int* __restrict__ edge_dst, int n_edges) {
    int e = blockIdx.x * blockDim.x + threadIdx.x;
    if (e < n_edges) atomicAdd(&g_deg[edge_dst[e]], 1);  // no return -> RED
}

// ---------------------------------------------------------------------------
// single-pass exclusive scan of g_deg -> g_offsets/g_cursor
// decoupled lookback, warp-parallel. All NB_SCAN blocks co-resident.
// ---------------------------------------------------------------------------
__global__ __launch_bounds__(SCAN_BLK) void scan_kernel(int n) {
    const int bid = blockIdx.x;
    const int tid = threadIdx.x;
    const int lane = tid & 31, wp = tid >> 5;
    const int i = bid * SCAN_BLK + tid;

    int v = (i < n) ? g_deg[i] : 0;

    // intra-block inclusive scan
    int x = v;
#pragma unroll
    for (int o = 1; o < 32; o <<= 1) {
        int t = __shfl_up_sync(0xffffffffu, x, o);
        if (lane >= o) x += t;
    }
    __shared__ int ws[32];
    __shared__ int s_prefix;
    if (lane == 31) ws[wp] = x;
    __syncthreads();
    if (wp == 0) {
        int s = ws[lane];
#pragma unroll
        for (int o = 1; o < 32; o <<= 1) {
            int t = __shfl_up_sync(0xffffffffu, s, o);
            if (lane >= o) s += t;
        }
        ws[lane] = s;
    }
    __syncthreads();
    const int incl = x + (wp > 0 ? ws[wp - 1] : 0);
    const int total = ws[31];

    if (bid == 0) {
        if (tid == 0) {
            atomicExch(&g_scanstate[0], 0x80000000u | (unsigned)total);
            s_prefix = 0;
        }
    } else if (wp == 0) {
        if (lane == 0)
            atomicExch(&g_scanstate[bid], 0x40000000u | (unsigned)total);
        // warp-parallel lookback
        int run = 0;
        int j = bid - 1;
        while (true) {
            int idx = j - lane;
            unsigned s;
            if (idx >= 0) {
                do { s = atomicOr(&g_scanstate[idx], 0u); }
                while ((s & 0xC0000000u) == 0u);
            } else {
                s = 0x80000000u;  // virtual prefix of value 0
            }
            unsigned bal = __ballot_sync(0xffffffffu, (s & 0x80000000u) != 0u);
            if (bal) {
                int firstP = __ffs(bal) - 1;  // nearest predecessor with full prefix
                int c = (lane <= firstP) ? (int)(s & 0x00FFFFFFu) : 0;
#pragma unroll
                for (int o = 16; o; o >>= 1) c += __shfl_down_sync(0xffffffffu, c, o);
                run += __shfl_sync(0xffffffffu, c, 0);
                break;
            } else {
                int c = (int)(s & 0x00FFFFFFu);
#pragma unroll
                for (int o = 16; o; o >>= 1) c += __shfl_down_sync(0xffffffffu, c, o);
                run += __shfl_sync(0xffffffffu, c, 0);
                j -= 32;
            }
        }
        if (lane == 0) {
            atomicExch(&g_scanstate[bid], 0x80000000u | (unsigned)(run + total));
            s_prefix = run;
        }
    }
    __syncthreads();

    const int excl = incl - v + s_prefix;
    if (i < n) { g_offsets[i] = excl; g_cursor[i] = excl; }
}

// ---------------------------------------------------------------------------
// fused: blocks [0, gemm_blocks) -> support = X @ W (8x4 register blocking)
//        blocks [gemm_blocks, +)  -> bucket edges by dst (grid-stride)
// ---------------------------------------------------------------------------
#define GEMM_THREADS 128
#define FILL_BLOCKS 256

__global__ __launch_bounds__(GEMM_THREADS) void fused_gemm_fill_kernel(
    const float* __restrict__ X, const float* __restrict__ W, int n_nodes,
    const int* __restrict__ edge_src, const int* __restrict__ edge_dst,
    const float* __restrict__ edge_weight, int n_edges, int gemm_blocks) {

    if (blockIdx.x >= gemm_blocks) {
        // ---- fill branch ----
        int nthreads = FILL_BLOCKS * GEMM_THREADS;
        int t0 = (blockIdx.x - gemm_blocks) * GEMM_THREADS + threadIdx.x;
        for (int e = t0; e < n_edges; e += nthreads) {
            int slot = atomicAdd(&g_cursor[edge_dst[e]], 1);
            g_edges[slot] = make_int2(edge_src[e], __float_as_int(edge_weight[e]));
        }
        return;
    }

    // ---- GEMM branch: 64x64 tile, 128 threads, 8x4 per thread ----
    __shared__ float Xt[D][D];  // Xt[k][r]
    __shared__ float sW[D][D];  // sW[k][c]

    const int tid = threadIdx.x;
    const int row0 = blockIdx.x * D;

    // load W: 1024 float4 / 128 threads = 8 each
    {
        const float4* W4 = reinterpret_cast<const float4*>(W);
        float4* sW4 = reinterpret_cast<float4*>(&sW[0][0]);
#pragma unroll
        for (int j = 0; j < 8; j++) sW4[tid + j * 128] = W4[tid + j * 128];
    }
    // load X tile transposed: thread t -> row r = t&63, k-half h = t>>6
    {
        const int r = tid & 63;
        const int h = tid >> 6;
        const int grow = row0 + r;
#pragma unroll
        for (int j = 0; j < 8; j++) {
            const int k = h * 32 + j * 4;
            float4 v = make_float4(0.f, 0.f, 0.f, 0.f);
            if (grow < n_nodes)
                v = *reinterpret_cast<const float4*>(X + grow * D + k);
            Xt[k + 0][r] = v.x; Xt[k + 1][r] = v.y;
            Xt[k + 2][r] = v.z; Xt[k + 3][r] = v.w;
        }
    }
    __syncthreads();

    const int tc = (tid & 15) * 4;  // 16 col groups
    const int tr = (tid >> 4) * 8;  // 8 row groups of 8

    float acc[8][4] = {};
#pragma unroll 8
    for (int k = 0; k < D; k++) {
        const float4 xa = *reinterpret_cast<const float4*>(&Xt[k][tr]);
        const float4 xb = *reinterpret_cast<const float4*>(&Xt[k][tr + 4]);
        const float4 w  = *reinterpret_cast<const float4*>(&sW[k][tc]);
        acc[0][0] += xa.x * w.x; acc[0][1] += xa.x * w.y; acc[0][2] += xa.x * w.z; acc[0][3] += xa.x * w.w;
        acc[1][0] += xa.y * w.x; acc[1][1] += xa.y * w.y; acc[1][2] += xa.y * w.z; acc[1][3] += xa.y * w.w;
        acc[2][0] += xa.z * w.x; acc[2][1] += xa.z * w.y; acc[2][2] += xa.z * w.z; acc[2][3] += xa.z * w.w;
        acc[3][0] += xa.w * w.x; acc[3][1] += xa.w * w.y; acc[3][2] += xa.w * w.z; acc[3][3] += xa.w * w.w;
        acc[4][0] += xb.x * w.x; acc[4][1] += xb.x * w.y; acc[4][2] += xb.x * w.z; acc[4][3] += xb.x * w.w;
        acc[5][0] += xb.y * w.x; acc[5][1] += xb.y * w.y; acc[5][2] += xb.y * w.z; acc[5][3] += xb.y * w.w;
        acc[6][0] += xb.z * w.x; acc[6][1] += xb.z * w.y; acc[6][2] += xb.z * w.z; acc[6][3] += xb.z * w.w;
        acc[7][0] += xb.w * w.x; acc[7][1] += xb.w * w.y; acc[7][2] += xb.w * w.z; acc[7][3] += xb.w * w.w;
    }

#pragma unroll
    for (int i = 0; i < 8; i++) {
        const int grow = row0 + tr + i;
        if (grow < n_nodes)
            *reinterpret_cast<float4*>(&g_support[grow * D + tc]) =
                make_float4(acc[i][0], acc[i][1], acc[i][2], acc[i][3]);
    }
}

// ---------------------------------------------------------------------------
// gather: one warp per node; lane l owns features [2l, 2l+1] (float2).
// out[n] = b + sum_e w_e * support[src_e]     (4x unrolled for MLP)
// ---------------------------------------------------------------------------
__global__ __launch_bounds__(256) void gather_kernel(
    const float* __restrict__ b, float* __restrict__ out, int n_nodes) {
    int warp = (blockIdx.x * blockDim.x + threadIdx.x) >> 5;
    int lane = threadIdx.x & 31;
    if (warp >= n_nodes) return;

    int start = g_offsets[warp];
    int end = g_cursor[warp];

    float2 a0 = make_float2(0.f, 0.f), a1 = make_float2(0.f, 0.f);
    float2 a2 = make_float2(0.f, 0.f), a3 = make_float2(0.f, 0.f);

    for (int p = start; p < end; p += 32) {
        int m = end - p; if (m > 32) m = 32;
        int2 ed = make_int2(0, 0);
        if (lane < m) ed = g_edges[p + lane];
        int j = 0;
        for (; j + 4 <= m; j += 4) {
            int s0 = __shfl_sync(0xffffffffu, ed.x, j + 0);
            int s1 = __shfl_sync(0xffffffffu, ed.x, j + 1);
            int s2 = __shfl_sync(0xffffffffu, ed.x, j + 2);
            int s3 = __shfl_sync(0xffffffffu, ed.x, j + 3);
            float w0 = __int_as_float(__shfl_sync(0xffffffffu, ed.y, j + 0));
            float w1 = __int_as_float(__shfl_sync(0xffffffffu, ed.y, j + 1));
            float w2 = __int_as_float(__shfl_sync(0xffffffffu, ed.y, j + 2));
            float w3 = __int_as_float(__shfl_sync(0xffffffffu, ed.y, j + 3));
            float2 v0 = reinterpret_cast<const float2*>(&g_support[s0 * D])[lane];
            float2 v1 = reinterpret_cast<const float2*>(&g_support[s1 * D])[lane];
            float2 v2 = reinterpret_cast<const float2*>(&g_support[s2 * D])[lane];
            float2 v3 = reinterpret_cast<const float2*>(&g_support[s3 * D])[lane];
            a0.x += w0 * v0.x; a0.y += w0 * v0.y;
            a1.x += w1 * v1.x; a1.y += w1 * v1.y;
            a2.x += w2 * v2.x; a2.y += w2 * v2.y;
            a3.x += w3 * v3.x; a3.y += w3 * v3.y;
        }
        for (; j < m; j++) {
            int s = __shfl_sync(0xffffffffu, ed.x, j);
            float wv = __int_as_float(__shfl_sync(0xffffffffu, ed.y, j));
            float2 v = reinterpret_cast<const float2*>(&g_support[s * D])[lane];
            a0.x += wv * v.x; a0.y += wv * v.y;
        }
    }
    float2 bb = reinterpret_cast<const float2*>(b)[lane];
    float2 r;
    r.x = (a0.x + a1.x) + (a2.x + a3.x) + bb.x;
    r.y = (a0.y + a1.y) + (a2.y + a3.y) + bb.y;
    reinterpret_cast<float2*>(out + warp * D)[lane] = r;
}

// ---------------------------------------------------------------------------
extern "C" void kernel_launch(void* const* d_in, const int* in_sizes, int n_in,
                              void* d_out, int out_size) {
    const float* X    = (const float*)d_in[0];
    const int*   esrc = (const int*)d_in[1];
    const int*   edst = (const int*)d_in[2];
    const float* ew   = (const float*)d_in[3];
    const float* W    = (const float*)d_in[4];
    const float* b    = (const float*)d_in[5];
    float*       out  = (float*)d_out;

    int n_nodes = in_sizes[0] / D;
    int n_edges = in_sizes[1];
    int nb_scan = (n_nodes + SCAN_BLK - 1) / SCAN_BLK;
    int gemm_blocks = (n_nodes + D - 1) / D;

    zero_kernel<<<(n_nodes + 255) / 256, 256>>>(n_nodes);
    count_kernel<<<(n_edges + 1023) / 1024, 1024>>>(edst, n_edges);
    scan_kernel<<<nb_scan, SCAN_BLK>>>(n_nodes);
    fused_gemm_fill_kernel<<<gemm_blocks + FILL_BLOCKS, GEMM_THREADS>>>(
        X, W, n_nodes, esrc, edst, ew, n_edges, gemm_blocks);
    gather_kernel<<<(n_nodes * 32 + 255) / 256, 256>>>(b, out, n_nodes);
}

// round 5
// speedup vs baseline: 1.0758x; 1.0758x over previous
#include <cuda_runtime.h>
#include <cuda_fp16.h>

#define D 64
#define MAX_NODES 50000
#define MAX_EDGES 800000
#define SCAN_BLK 1024
#define NB_SCAN ((MAX_NODES + SCAN_BLK - 1) / SCAN_BLK)   // 49

// ---- scratch ----
__device__ __half   g_support_h[MAX_NODES * D];  // X @ W in fp16 (6.4 MB)
__device__ int      g_deg[MAX_NODES];
__device__ int      g_offsets[MAX_NODES];
__device__ int      g_cursor[MAX_NODES];
__device__ unsigned g_scanstate[NB_SCAN];
__device__ int2     g_edges[MAX_EDGES];          // (src, bitcast(w)) bucketed by dst

// ---------------------------------------------------------------------------
// count: 4 edges per thread via int4
// ---------------------------------------------------------------------------
__global__ void count_kernel(const int* __restrict__ edge_dst, int n_edges) {
    int t = blockIdx.x * blockDim.x + threadIdx.x;
    int e4 = t * 4;
    if (e4 + 3 < n_edges) {
        int4 d = *reinterpret_cast<const int4*>(edge_dst + e4);
        atomicAdd(&g_deg[d.x], 1);
        atomicAdd(&g_deg[d.y], 1);
        atomicAdd(&g_deg[d.z], 1);
        atomicAdd(&g_deg[d.w], 1);
    } else {
        for (int e = e4; e < n_edges; e++) atomicAdd(&g_deg[edge_dst[e]], 1);
    }
}

// ---------------------------------------------------------------------------
// single-pass exclusive scan (decoupled lookback, warp-parallel)
// ---------------------------------------------------------------------------
__global__ __launch_bounds__(SCAN_BLK) void scan_kernel(int n) {
    const int bid = blockIdx.x;
    const int tid = threadIdx.x;
    const int lane = tid & 31, wp = tid >> 5;
    const int i = bid * SCAN_BLK + tid;

    int v = (i < n) ? g_deg[i] : 0;

    int x = v;
#pragma unroll
    for (int o = 1; o < 32; o <<= 1) {
        int t = __shfl_up_sync(0xffffffffu, x, o);
        if (lane >= o) x += t;
    }
    __shared__ int ws[32];
    __shared__ int s_prefix;
    if (lane == 31) ws[wp] = x;
    __syncthreads();
    if (wp == 0) {
        int s = ws[lane];
#pragma unroll
        for (int o = 1; o < 32; o <<= 1) {
            int t = __shfl_up_sync(0xffffffffu, s, o);
            if (lane >= o) s += t;
        }
        ws[lane] = s;
    }
    __syncthreads();
    const int incl = x + (wp > 0 ? ws[wp - 1] : 0);
    const int total = ws[31];

    if (bid == 0) {
        if (tid == 0) {
            atomicExch(&g_scanstate[0], 0x80000000u | (unsigned)total);
            s_prefix = 0;
        }
    } else if (wp == 0) {
        if (lane == 0)
            atomicExch(&g_scanstate[bid], 0x40000000u | (unsigned)total);
        int run = 0;
        int j = bid - 1;
        while (true) {
            int idx = j - lane;
            unsigned s;
            if (idx >= 0) {
                do { s = atomicOr(&g_scanstate[idx], 0u); }
                while ((s & 0xC0000000u) == 0u);
            } else {
                s = 0x80000000u;
            }
            unsigned bal = __ballot_sync(0xffffffffu, (s & 0x80000000u) != 0u);
            if (bal) {
                int firstP = __ffs(bal) - 1;
                int c = (lane <= firstP) ? (int)(s & 0x00FFFFFFu) : 0;
#pragma unroll
                for (int o = 16; o; o >>= 1) c += __shfl_down_sync(0xffffffffu, c, o);
                run += __shfl_sync(0xffffffffu, c, 0);
                break;
            } else {
                int c = (int)(s & 0x00FFFFFFu);
#pragma unroll
                for (int o = 16; o; o >>= 1) c += __shfl_down_sync(0xffffffffu, c, o);
                run += __shfl_sync(0xffffffffu, c, 0);
                j -= 32;
            }
        }
        if (lane == 0) {
            atomicExch(&g_scanstate[bid], 0x80000000u | (unsigned)(run + total));
            s_prefix = run;
        }
    }
    __syncthreads();

    const int excl = incl - v + s_prefix;
    if (i < n) { g_offsets[i] = excl; g_cursor[i] = excl; }
}

// ---------------------------------------------------------------------------
// fill: bucket edges by dst
// ---------------------------------------------------------------------------
__global__ void fill_kernel(const int* __restrict__ edge_src,
                            const int* __restrict__ edge_dst,
                            const float* __restrict__ edge_weight, int n_edges) {
    int e = blockIdx.x * blockDim.x + threadIdx.x;
    if (e >= n_edges) return;
    int slot = atomicAdd(&g_cursor[edge_dst[e]], 1);
    g_edges[slot] = make_int2(edge_src[e], __float_as_int(edge_weight[e]));
}

// ---------------------------------------------------------------------------
// GEMM: support = X @ W, fp32 accumulate, fp16 store.
// 128-row x 64-col tile, 256 threads, 8x4 register blocking per thread.
// ---------------------------------------------------------------------------
#define TILE_R 128

__global__ __launch_bounds__(256) void gcn_gemm_kernel(
    const float* __restrict__ X, const float* __restrict__ W, int n_nodes) {
    __shared__ float Xt[D][TILE_R];  // Xt[k][r]  (32 KB)
    __shared__ float sW[D][D];       // sW[k][c]  (16 KB)

    const int tid = threadIdx.x;
    const int row0 = blockIdx.x * TILE_R;

    // load W: 1024 float4 / 256 threads = 4 each
    {
        const float4* W4 = reinterpret_cast<const float4*>(W);
        float4* sW4 = reinterpret_cast<float4*>(&sW[0][0]);
#pragma unroll
        for (int j = 0; j < 4; j++) sW4[tid + j * 256] = W4[tid + j * 256];
    }
    // load X tile transposed: thread t -> row r = t&127, k-half h = t>>7
    {
        const int r = tid & 127;
        const int h = tid >> 7;       // 0..1, covers 8 chunks each
        const int grow = row0 + r;
#pragma unroll
        for (int j = 0; j < 8; j++) {
            const int k = (h * 8 + j) * 4;
            float4 v = make_float4(0.f, 0.f, 0.f, 0.f);
            if (grow < n_nodes)
                v = *reinterpret_cast<const float4*>(X + grow * D + k);
            Xt[k + 0][r] = v.x; Xt[k + 1][r] = v.y;
            Xt[k + 2][r] = v.z; Xt[k + 3][r] = v.w;
        }
    }
    __syncthreads();

    const int tc = (tid & 15) * 4;   // 16 col groups
    const int tr = (tid >> 4) * 8;   // 16 row groups of 8

    float acc[8][4] = {};
#pragma unroll 8
    for (int k = 0; k < D; k++) {
        const float4 xa = *reinterpret_cast<const float4*>(&Xt[k][tr]);
        const float4 xb = *reinterpret_cast<const float4*>(&Xt[k][tr + 4]);
        const float4 w  = *reinterpret_cast<const float4*>(&sW[k][tc]);
        acc[0][0] += xa.x * w.x; acc[0][1] += xa.x * w.y; acc[0][2] += xa.x * w.z; acc[0][3] += xa.x * w.w;
        acc[1][0] += xa.y * w.x; acc[1][1] += xa.y * w.y; acc[1][2] += xa.y * w.z; acc[1][3] += xa.y * w.w;
        acc[2][0] += xa.z * w.x; acc[2][1] += xa.z * w.y; acc[2][2] += xa.z * w.z; acc[2][3] += xa.z * w.w;
        acc[3][0] += xa.w * w.x; acc[3][1] += xa.w * w.y; acc[3][2] += xa.w * w.z; acc[3][3] += xa.w * w.w;
        acc[4][0] += xb.x * w.x; acc[4][1] += xb.x * w.y; acc[4][2] += xb.x * w.z; acc[4][3] += xb.x * w.w;
        acc[5][0] += xb.y * w.x; acc[5][1] += xb.y * w.y; acc[5][2] += xb.y * w.z; acc[5][3] += xb.y * w.w;
        acc[6][0] += xb.z * w.x; acc[6][1] += xb.z * w.y; acc[6][2] += xb.z * w.z; acc[6][3] += xb.z * w.w;
        acc[7][0] += xb.w * w.x; acc[7][1] += xb.w * w.y; acc[7][2] += xb.w * w.z; acc[7][3] += xb.w * w.w;
    }

#pragma unroll
    for (int i = 0; i < 8; i++) {
        const int grow = row0 + tr + i;
        if (grow < n_nodes) {
            __half2 h0 = __floats2half2_rn(acc[i][0], acc[i][1]);
            __half2 h1 = __floats2half2_rn(acc[i][2], acc[i][3]);
            uint2 pk = make_uint2(*reinterpret_cast<unsigned*>(&h0),
                                  *reinterpret_cast<unsigned*>(&h1));
            *reinterpret_cast<uint2*>(&g_support_h[grow * D + tc]) = pk;
        }
    }
}

// ---------------------------------------------------------------------------
// gather: one warp per node; lane l owns features [2l, 2l+1] (one half2).
// out[n] = b + sum_e w_e * support_h[src_e]     (fp32 accumulate)
// ---------------------------------------------------------------------------
__global__ __launch_bounds__(256) void gather_kernel(
    const float* __restrict__ b, float* __restrict__ out, int n_nodes) {
    int warp = (blockIdx.x * blockDim.x + threadIdx.x) >> 5;
    int lane = threadIdx.x & 31;
    if (warp >= n_nodes) return;

    int start = g_offsets[warp];
    int end = g_cursor[warp];

    float2 a0 = make_float2(0.f, 0.f), a1 = make_float2(0.f, 0.f);
    float2 a2 = make_float2(0.f, 0.f), a3 = make_float2(0.f, 0.f);

    const __half2* sup2 = reinterpret_cast<const __half2*>(g_support_h);

    for (int p = start; p < end; p += 32) {
        int m = end - p; if (m > 32) m = 32;
        int2 ed = make_int2(0, 0);
        if (lane < m) ed = g_edges[p + lane];
        int j = 0;
        for (; j + 4 <= m; j += 4) {
            int s0 = __shfl_sync(0xffffffffu, ed.x, j + 0);
            int s1 = __shfl_sync(0xffffffffu, ed.x, j + 1);
            int s2 = __shfl_sync(0xffffffffu, ed.x, j + 2);
            int s3 = __shfl_sync(0xffffffffu, ed.x, j + 3);
            float w0 = __int_as_float(__shfl_sync(0xffffffffu, ed.y, j + 0));
            float w1 = __int_as_float(__shfl_sync(0xffffffffu, ed.y, j + 1));
            float w2 = __int_as_float(__shfl_sync(0xffffffffu, ed.y, j + 2));
            float w3 = __int_as_float(__shfl_sync(0xffffffffu, ed.y, j + 3));
            float2 v0 = __half22float2(sup2[s0 * (D / 2) + lane]);
            float2 v1 = __half22float2(sup2[s1 * (D / 2) + lane]);
            float2 v2 = __half22float2(sup2[s2 * (D / 2) + lane]);
            float2 v3 = __half22float2(sup2[s3 * (D / 2) + lane]);
            a0.x += w0 * v0.x; a0.y += w0 * v0.y;
            a1.x += w1 * v1.x; a1.y += w1 * v1.y;
            a2.x += w2 * v2.x; a2.y += w2 * v2.y;
            a3.x += w3 * v3.x; a3.y += w3 * v3.y;
        }
        for (; j < m; j++) {
            int s = __shfl_sync(0xffffffffu, ed.x, j);
            float wv = __int_as_float(__shfl_sync(0xffffffffu, ed.y, j));
            float2 v = __half22float2(sup2[s * (D / 2) + lane]);
            a0.x += wv * v.x; a0.y += wv * v.y;
        }
    }
    float2 bb = reinterpret_cast<const float2*>(b)[lane];
    float2 r;
    r.x = (a0.x + a1.x) + (a2.x + a3.x) + bb.x;
    r.y = (a0.y + a1.y) + (a2.y + a3.y) + bb.y;
    reinterpret_cast<float2*>(out + warp * D)[lane] = r;
}

// ---------------------------------------------------------------------------
extern "C" void kernel_launch(void* const* d_in, const int* in_sizes, int n_in,
                              void* d_out, int out_size) {
    const float* X    = (const float*)d_in[0];
    const int*   esrc = (const int*)d_in[1];
    const int*   edst = (const int*)d_in[2];
    const float* ew   = (const float*)d_in[3];
    const float* W    = (const float*)d_in[4];
    const float* b    = (const float*)d_in[5];
    float*       out  = (float*)d_out;

    int n_nodes = in_sizes[0] / D;
    int n_edges = in_sizes[1];
    int nb_scan = (n_nodes + SCAN_BLK - 1) / SCAN_BLK;

    // zero deg + scan state via memset nodes (no kernel launch)
    void* p_deg = nullptr; void* p_state = nullptr;
    cudaGetSymbolAddress(&p_deg, g_deg);
    cudaGetSymbolAddress(&p_state, g_scanstate);
    cudaMemsetAsync(p_deg, 0, n_nodes * sizeof(int));
    cudaMemsetAsync(p_state, 0, NB_SCAN * sizeof(unsigned));

    count_kernel<<<(n_edges / 4 + 255) / 256, 256>>>(edst, n_edges);
    scan_kernel<<<nb_scan, SCAN_BLK>>>(n_nodes);
    fill_kernel<<<(n_edges + 255) / 256, 256>>>(esrc, edst, ew, n_edges);

    gcn_gemm_kernel<<<(n_nodes + TILE_R - 1) / TILE_R, 256>>>(X, W, n_nodes);

    gather_kernel<<<(n_nodes * 32 + 255) / 256, 256>>>(b, out, n_nodes);
}

// round 6
// speedup vs baseline: 1.1525x; 1.0713x over previous
#include <cuda_runtime.h>
#include <cuda_fp16.h>

#define D 64
#define MAX_NODES 50000
#define MAX_EDGES 800000
#define SCAN_BLK 1024
#define NB_SCAN ((MAX_NODES + SCAN_BLK - 1) / SCAN_BLK)   // 49

// ---- scratch ----
__device__ __half g_support_h[MAX_NODES * D];  // X @ W in fp16 (6.4 MB)
__device__ int    g_deg[MAX_NODES];
__device__ int    g_offsets[MAX_NODES];
__device__ int    g_cursor[MAX_NODES];
__device__ int    g_blocksum[NB_SCAN];
__device__ int    g_blockoff[NB_SCAN];
__device__ int2   g_edges[MAX_EDGES];          // (src, bitcast(w)) bucketed by dst

// ======================= CSR build (R3 chain, verbatim) =====================
__global__ void zero_deg_kernel(int n) {
    int i = blockIdx.x * blockDim.x + threadIdx.x;
    if (i < n) g_deg[i] = 0;
}

__global__ void count_kernel(const int* __restrict__ edge_dst, int n_edges) {
    int e = blockIdx.x * blockDim.x + threadIdx.x;
    if (e < n_edges) atomicAdd(&g_deg[edge_dst[e]], 1);  // no return -> RED
}

__global__ __launch_bounds__(SCAN_BLK) void scan_sums_kernel(int n) {
    int i = blockIdx.x * SCAN_BLK + threadIdx.x;
    int v = (i < n) ? g_deg[i] : 0;
#pragma unroll
    for (int o = 16; o; o >>= 1) v += __shfl_down_sync(0xffffffffu, v, o);
    __shared__ int ws[32];
    if ((threadIdx.x & 31) == 0) ws[threadIdx.x >> 5] = v;
    __syncthreads();
    if (threadIdx.x < 32) {
        int s = ws[threadIdx.x];
#pragma unroll
        for (int o = 16; o; o >>= 1) s += __shfl_down_sync(0xffffffffu, s, o);
        if (threadIdx.x == 0) g_blocksum[blockIdx.x] = s;
    }
}

__global__ void scan_partials_kernel(int nb) {
    if (threadIdx.x == 0 && blockIdx.x == 0) {
        int run = 0;
        for (int i = 0; i < nb; i++) { g_blockoff[i] = run; run += g_blocksum[i]; }
    }
}

__global__ __launch_bounds__(SCAN_BLK) void scan_final_kernel(int n) {
    int i = blockIdx.x * SCAN_BLK + threadIdx.x;
    int v = (i < n) ? g_deg[i] : 0;
    int lane = threadIdx.x & 31, wp = threadIdx.x >> 5;
    int x = v;
#pragma unroll
    for (int o = 1; o < 32; o <<= 1) {
        int t = __shfl_up_sync(0xffffffffu, x, o);
        if (lane >= o) x += t;
    }
    __shared__ int ws[32];
    if (lane == 31) ws[wp] = x;
    __syncthreads();
    if (wp == 0) {
        int s = ws[lane];
#pragma unroll
        for (int o = 1; o < 32; o <<= 1) {
            int t = __shfl_up_sync(0xffffffffu, s, o);
            if (lane >= o) s += t;
        }
        ws[lane] = s;
    }
    __syncthreads();
    int excl = x - v + (wp > 0 ? ws[wp - 1] : 0) + g_blockoff[blockIdx.x];
    if (i < n) { g_offsets[i] = excl; g_cursor[i] = excl; }
}

__global__ void fill_kernel(const int* __restrict__ edge_src,
                            const int* __restrict__ edge_dst,
                            const float* __restrict__ edge_weight, int n_edges) {
    int e = blockIdx.x * blockDim.x + threadIdx.x;
    if (e >= n_edges) return;
    int slot = atomicAdd(&g_cursor[edge_dst[e]], 1);
    g_edges[slot] = make_int2(edge_src[e], __float_as_int(edge_weight[e]));
}

// ============= GEMM (R5, measured 17.1us): fp32 accum, fp16 store ==========
#define TILE_R 128

__global__ __launch_bounds__(256) void gcn_gemm_kernel(
    const float* __restrict__ X, const float* __restrict__ W, int n_nodes) {
    __shared__ float Xt[D][TILE_R];
    __shared__ float sW[D][D];

    const int tid = threadIdx.x;
    const int row0 = blockIdx.x * TILE_R;

    {
        const float4* W4 = reinterpret_cast<const float4*>(W);
        float4* sW4 = reinterpret_cast<float4*>(&sW[0][0]);
#pragma unroll
        for (int j = 0; j < 4; j++) sW4[tid + j * 256] = W4[tid + j * 256];
    }
    {
        const int r = tid & 127;
        const int h = tid >> 7;
        const int grow = row0 + r;
#pragma unroll
        for (int j = 0; j < 8; j++) {
            const int k = (h * 8 + j) * 4;
            float4 v = make_float4(0.f, 0.f, 0.f, 0.f);
            if (grow < n_nodes)
                v = *reinterpret_cast<const float4*>(X + grow * D + k);
            Xt[k + 0][r] = v.x; Xt[k + 1][r] = v.y;
            Xt[k + 2][r] = v.z; Xt[k + 3][r] = v.w;
        }
    }
    __syncthreads();

    const int tc = (tid & 15) * 4;
    const int tr = (tid >> 4) * 8;

    float acc[8][4] = {};
#pragma unroll 8
    for (int k = 0; k < D; k++) {
        const float4 xa = *reinterpret_cast<const float4*>(&Xt[k][tr]);
        const float4 xb = *reinterpret_cast<const float4*>(&Xt[k][tr + 4]);
        const float4 w  = *reinterpret_cast<const float4*>(&sW[k][tc]);
        acc[0][0] += xa.x * w.x; acc[0][1] += xa.x * w.y; acc[0][2] += xa.x * w.z; acc[0][3] += xa.x * w.w;
        acc[1][0] += xa.y * w.x; acc[1][1] += xa.y * w.y; acc[1][2] += xa.y * w.z; acc[1][3] += xa.y * w.w;
        acc[2][0] += xa.z * w.x; acc[2][1] += xa.z * w.y; acc[2][2] += xa.z * w.z; acc[2][3] += xa.z * w.w;
        acc[3][0] += xa.w * w.x; acc[3][1] += xa.w * w.y; acc[3][2] += xa.w * w.z; acc[3][3] += xa.w * w.w;
        acc[4][0] += xb.x * w.x; acc[4][1] += xb.x * w.y; acc[4][2] += xb.x * w.z; acc[4][3] += xb.x * w.w;
        acc[5][0] += xb.y * w.x; acc[5][1] += xb.y * w.y; acc[5][2] += xb.y * w.z; acc[5][3] += xb.y * w.w;
        acc[6][0] += xb.z * w.x; acc[6][1] += xb.z * w.y; acc[6][2] += xb.z * w.z; acc[6][3] += xb.z * w.w;
        acc[7][0] += xb.w * w.x; acc[7][1] += xb.w * w.y; acc[7][2] += xb.w * w.z; acc[7][3] += xb.w * w.w;
    }

#pragma unroll
    for (int i = 0; i < 8; i++) {
        const int grow = row0 + tr + i;
        if (grow < n_nodes) {
            __half2 h0 = __floats2half2_rn(acc[i][0], acc[i][1]);
            __half2 h1 = __floats2half2_rn(acc[i][2], acc[i][3]);
            uint2 pk = make_uint2(*reinterpret_cast<unsigned*>(&h0),
                                  *reinterpret_cast<unsigned*>(&h1));
            *reinterpret_cast<uint2*>(&g_support_h[grow * D + tc]) = pk;
        }
    }
}

// ===================== gather (R5 fp16 version, validated) ==================
__global__ __launch_bounds__(256) void gather_kernel(
    const float* __restrict__ b, float* __restrict__ out, int n_nodes) {
    int warp = (blockIdx.x * blockDim.x + threadIdx.x) >> 5;
    int lane = threadIdx.x & 31;
    if (warp >= n_nodes) return;

    int start = g_offsets[warp];
    int end = g_cursor[warp];

    float2 a0 = make_float2(0.f, 0.f), a1 = make_float2(0.f, 0.f);
    float2 a2 = make_float2(0.f, 0.f), a3 = make_float2(0.f, 0.f);

    const __half2* sup2 = reinterpret_cast<const __half2*>(g_support_h);

    for (int p = start; p < end; p += 32) {
        int m = end - p; if (m > 32) m = 32;
        int2 ed = make_int2(0, 0);
        if (lane < m) ed = g_edges[p + lane];
        int j = 0;
        for (; j + 4 <= m; j += 4) {
            int s0 = __shfl_sync(0xffffffffu, ed.x, j + 0);
            int s1 = __shfl_sync(0xffffffffu, ed.x, j + 1);
            int s2 = __shfl_sync(0xffffffffu, ed.x, j + 2);
            int s3 = __shfl_sync(0xffffffffu, ed.x, j + 3);
            float w0 = __int_as_float(__shfl_sync(0xffffffffu, ed.y, j + 0));
            float w1 = __int_as_float(__shfl_sync(0xffffffffu, ed.y, j + 1));
            float w2 = __int_as_float(__shfl_sync(0xffffffffu, ed.y, j + 2));
            float w3 = __int_as_float(__shfl_sync(0xffffffffu, ed.y, j + 3));
            float2 v0 = __half22float2(sup2[s0 * (D / 2) + lane]);
            float2 v1 = __half22float2(sup2[s1 * (D / 2) + lane]);
            float2 v2 = __half22float2(sup2[s2 * (D / 2) + lane]);
            float2 v3 = __half22float2(sup2[s3 * (D / 2) + lane]);
            a0.x += w0 * v0.x; a0.y += w0 * v0.y;
            a1.x += w1 * v1.x; a1.y += w1 * v1.y;
            a2.x += w2 * v2.x; a2.y += w2 * v2.y;
            a3.x += w3 * v3.x; a3.y += w3 * v3.y;
        }
        for (; j < m; j++) {
            int s = __shfl_sync(0xffffffffu, ed.x, j);
            float wv = __int_as_float(__shfl_sync(0xffffffffu, ed.y, j));
            float2 v = __half22float2(sup2[s * (D / 2) + lane]);
            a0.x += wv * v.x; a0.y += wv * v.y;
        }
    }
    float2 bb = reinterpret_cast<const float2*>(b)[lane];
    float2 r;
    r.x = (a0.x + a1.x) + (a2.x + a3.x) + bb.x;
    r.y = (a0.y + a1.y) + (a2.y + a3.y) + bb.y;
    reinterpret_cast<float2*>(out + warp * D)[lane] = r;
}

// ---------------------------------------------------------------------------
extern "C" void kernel_launch(void* const* d_in, const int* in_sizes, int n_in,
                              void* d_out, int out_size) {
    const float* X    = (const float*)d_in[0];
    const int*   esrc = (const int*)d_in[1];
    const int*   edst = (const int*)d_in[2];
    const float* ew   = (const float*)d_in[3];
    const float* W    = (const float*)d_in[4];
    const float* b    = (const float*)d_in[5];
    float*       out  = (float*)d_out;

    int n_nodes = in_sizes[0] / D;
    int n_edges = in_sizes[1];
    int nb_scan = (n_nodes + SCAN_BLK - 1) / SCAN_BLK;

    // one-time side stream + events (host resources only; no device memory)
    static cudaStream_t s_side = nullptr;
    static cudaEvent_t s_fork = nullptr, s_join = nullptr;
    if (!s_side) {
        cudaStreamCreateWithFlags(&s_side, cudaStreamNonBlocking);
        cudaEventCreateWithFlags(&s_fork, cudaEventDisableTiming);
        cudaEventCreateWithFlags(&s_join, cudaEventDisableTiming);
    }

    // fork: GEMM runs concurrently with the CSR build
    cudaEventRecord(s_fork, 0);
    cudaStreamWaitEvent(s_side, s_fork, 0);
    gcn_gemm_kernel<<<(n_nodes + TILE_R - 1) / TILE_R, 256, 0, s_side>>>(X, W, n_nodes);
    cudaEventRecord(s_join, s_side);

    // CSR build on the main (capture) stream
    zero_deg_kernel<<<(n_nodes + 255) / 256, 256>>>(n_nodes);
    count_kernel<<<(n_edges + 255) / 256, 256>>>(edst, n_edges);
    scan_sums_kernel<<<nb_scan, SCAN_BLK>>>(n_nodes);
    scan_partials_kernel<<<1, 32>>>(nb_scan);
    scan_final_kernel<<<nb_scan, SCAN_BLK>>>(n_nodes);
    fill_kernel<<<(n_edges + 255) / 256, 256>>>(esrc, edst, ew, n_edges);

    // join: gather needs both the CSR and the support matrix
    cudaStreamWaitEvent(0, s_join, 0);
    gather_kernel<<<(n_nodes * 32 + 255) / 256, 256>>>(b, out, n_nodes);
}

// round 7
// speedup vs baseline: 1.3527x; 1.1737x over previous
#include <cuda_runtime.h>
#include <cuda_fp16.h>

#define D 64
#define MAX_NODES 50000
#define CAP 128            // bucket capacity per node (Poisson(16) degrees)
#define OVF_CAP 8192

// ---- scratch ----
__device__ __half g_support_h[MAX_NODES * D];       // X @ W in fp16 (6.4 MB)
__device__ int    g_cnt[MAX_NODES];                 // per-dst degree counters
__device__ int2   g_bucket[MAX_NODES * CAP];        // (src, bitcast(w)) per dst (51.2 MB)
__device__ int    g_novf;
__device__ int4   g_ovf[OVF_CAP];                   // (dst, src, w, -) spill

// ---------------------------------------------------------------------------
// single-pass bucket fill
// ---------------------------------------------------------------------------
__global__ void fill_kernel(const int* __restrict__ edge_src,
                            const int* __restrict__ edge_dst,
                            const float* __restrict__ edge_weight, int n_edges) {
    int e = blockIdx.x * blockDim.x + threadIdx.x;
    if (e >= n_edges) return;
    int d = edge_dst[e];
    int slot = atomicAdd(&g_cnt[d], 1);
    if (slot < CAP) {
        g_bucket[d * CAP + slot] = make_int2(edge_src[e], __float_as_int(edge_weight[e]));
    } else {
        int o = atomicAdd(&g_novf, 1);
        if (o < OVF_CAP)
            g_ovf[o] = make_int4(d, edge_src[e], __float_as_int(edge_weight[e]), 0);
    }
}

// ---------------------------------------------------------------------------
// GEMM: support = X @ W, fp32 accumulate, fp16 store.
// 128-row x 64-col tile, 256 threads, 8x4 register blocking.
// ---------------------------------------------------------------------------
#define TILE_R 128

__global__ __launch_bounds__(256) void gcn_gemm_kernel(
    const float* __restrict__ X, const float* __restrict__ W, int n_nodes) {
    __shared__ float Xt[D][TILE_R];
    __shared__ float sW[D][D];

    const int tid = threadIdx.x;
    const int row0 = blockIdx.x * TILE_R;

    {
        const float4* W4 = reinterpret_cast<const float4*>(W);
        float4* sW4 = reinterpret_cast<float4*>(&sW[0][0]);
#pragma unroll
        for (int j = 0; j < 4; j++) sW4[tid + j * 256] = W4[tid + j * 256];
    }
    {
        const int r = tid & 127;
        const int h = tid >> 7;
        const int grow = row0 + r;
#pragma unroll
        for (int j = 0; j < 8; j++) {
            const int k = (h * 8 + j) * 4;
            float4 v = make_float4(0.f, 0.f, 0.f, 0.f);
            if (grow < n_nodes)
                v = *reinterpret_cast<const float4*>(X + grow * D + k);
            Xt[k + 0][r] = v.x; Xt[k + 1][r] = v.y;
            Xt[k + 2][r] = v.z; Xt[k + 3][r] = v.w;
        }
    }
    __syncthreads();

    const int tc = (tid & 15) * 4;
    const int tr = (tid >> 4) * 8;

    float acc[8][4] = {};
#pragma unroll 8
    for (int k = 0; k < D; k++) {
        const float4 xa = *reinterpret_cast<const float4*>(&Xt[k][tr]);
        const float4 xb = *reinterpret_cast<const float4*>(&Xt[k][tr + 4]);
        const float4 w  = *reinterpret_cast<const float4*>(&sW[k][tc]);
        acc[0][0] += xa.x * w.x; acc[0][1] += xa.x * w.y; acc[0][2] += xa.x * w.z; acc[0][3] += xa.x * w.w;
        acc[1][0] += xa.y * w.x; acc[1][1] += xa.y * w.y; acc[1][2] += xa.y * w.z; acc[1][3] += xa.y * w.w;
        acc[2][0] += xa.z * w.x; acc[2][1] += xa.z * w.y; acc[2][2] += xa.z * w.z; acc[2][3] += xa.z * w.w;
        acc[3][0] += xa.w * w.x; acc[3][1] += xa.w * w.y; acc[3][2] += xa.w * w.z; acc[3][3] += xa.w * w.w;
        acc[4][0] += xb.x * w.x; acc[4][1] += xb.x * w.y; acc[4][2] += xb.x * w.z; acc[4][3] += xb.x * w.w;
        acc[5][0] += xb.y * w.x; acc[5][1] += xb.y * w.y; acc[5][2] += xb.y * w.z; acc[5][3] += xb.y * w.w;
        acc[6][0] += xb.z * w.x; acc[6][1] += xb.z * w.y; acc[6][2] += xb.z * w.z; acc[6][3] += xb.z * w.w;
        acc[7][0] += xb.w * w.x; acc[7][1] += xb.w * w.y; acc[7][2] += xb.w * w.z; acc[7][3] += xb.w * w.w;
    }

#pragma unroll
    for (int i = 0; i < 8; i++) {
        const int grow = row0 + tr + i;
        if (grow < n_nodes) {
            __half2 h0 = __floats2half2_rn(acc[i][0], acc[i][1]);
            __half2 h1 = __floats2half2_rn(acc[i][2], acc[i][3]);
            uint2 pk = make_uint2(*reinterpret_cast<unsigned*>(&h0),
                                  *reinterpret_cast<unsigned*>(&h1));
            *reinterpret_cast<uint2*>(&g_support_h[grow * D + tc]) = pk;
        }
    }
}

// ---------------------------------------------------------------------------
// gather: one warp per node; lane l owns features [2l, 2l+1] (one half2).
// out[n] = b + sum_e w_e * support_h[src_e]     (fp32 accumulate)
// ---------------------------------------------------------------------------
__global__ __launch_bounds__(256) void gather_kernel(
    const float* __restrict__ b, float* __restrict__ out, int n_nodes) {
    int warp = (blockIdx.x * blockDim.x + threadIdx.x) >> 5;
    int lane = threadIdx.x & 31;
    if (warp >= n_nodes) return;

    int deg = g_cnt[warp];
    if (deg > CAP) deg = CAP;
    const int2* row = &g_bucket[warp * CAP];

    float2 a0 = make_float2(0.f, 0.f), a1 = make_float2(0.f, 0.f);
    float2 a2 = make_float2(0.f, 0.f), a3 = make_float2(0.f, 0.f);

    const __half2* sup2 = reinterpret_cast<const __half2*>(g_support_h);

    for (int p = 0; p < deg; p += 32) {
        int m = deg - p; if (m > 32) m = 32;
        int2 ed = make_int2(0, 0);
        if (lane < m) ed = row[p + lane];
        int j = 0;
        for (; j + 4 <= m; j += 4) {
            int s0 = __shfl_sync(0xffffffffu, ed.x, j + 0);
            int s1 = __shfl_sync(0xffffffffu, ed.x, j + 1);
            int s2 = __shfl_sync(0xffffffffu, ed.x, j + 2);
            int s3 = __shfl_sync(0xffffffffu, ed.x, j + 3);
            float w0 = __int_as_float(__shfl_sync(0xffffffffu, ed.y, j + 0));
            float w1 = __int_as_float(__shfl_sync(0xffffffffu, ed.y, j + 1));
            float w2 = __int_as_float(__shfl_sync(0xffffffffu, ed.y, j + 2));
            float w3 = __int_as_float(__shfl_sync(0xffffffffu, ed.y, j + 3));
            float2 v0 = __half22float2(sup2[s0 * (D / 2) + lane]);
            float2 v1 = __half22float2(sup2[s1 * (D / 2) + lane]);
            float2 v2 = __half22float2(sup2[s2 * (D / 2) + lane]);
            float2 v3 = __half22float2(sup2[s3 * (D / 2) + lane]);
            a0.x += w0 * v0.x; a0.y += w0 * v0.y;
            a1.x += w1 * v1.x; a1.y += w1 * v1.y;
            a2.x += w2 * v2.x; a2.y += w2 * v2.y;
            a3.x += w3 * v3.x; a3.y += w3 * v3.y;
        }
        for (; j < m; j++) {
            int s = __shfl_sync(0xffffffffu, ed.x, j);
            float wv = __int_as_float(__shfl_sync(0xffffffffu, ed.y, j));
            float2 v = __half22float2(sup2[s * (D / 2) + lane]);
            a0.x += wv * v.x; a0.y += wv * v.y;
        }
    }
    float2 bb = reinterpret_cast<const float2*>(b)[lane];
    float2 r;
    r.x = (a0.x + a1.x) + (a2.x + a3.x) + bb.x;
    r.y = (a0.y + a1.y) + (a2.y + a3.y) + bb.y;
    reinterpret_cast<float2*>(out + warp * D)[lane] = r;
}

// ---------------------------------------------------------------------------
// overflow cleanup: REDG-add any spilled edges onto out (normally 0 edges).
// 16 threads per edge, each one red.v4.
// ---------------------------------------------------------------------------
__global__ void ovf_kernel(float* __restrict__ out) {
    int n = g_novf;
    if (n > OVF_CAP) n = OVF_CAP;
    int total = n * 16;
    for (int i = blockIdx.x * blockDim.x + threadIdx.x; i < total;
         i += gridDim.x * blockDim.x) {
        int e = i >> 4;
        int q = (i & 15) << 2;
        int4 ed = g_ovf[e];
        float w = __int_as_float(ed.z);
        const __half2* s2 =
            reinterpret_cast<const __half2*>(g_support_h) + ed.y * (D / 2) + (q >> 1);
        float2 v0 = __half22float2(s2[0]);
        float2 v1 = __half22float2(s2[1]);
        float* p = out + ed.x * D + q;
        asm volatile("red.global.add.v4.f32 [%0], {%1, %2, %3, %4};"
                     :: "l"(p), "f"(w * v0.x), "f"(w * v0.y),
                        "f"(w * v1.x), "f"(w * v1.y)
                     : "memory");
    }
}

// ---------------------------------------------------------------------------
extern "C" void kernel_launch(void* const* d_in, const int* in_sizes, int n_in,
                              void* d_out, int out_size) {
    const float* X    = (const float*)d_in[0];
    const int*   esrc = (const int*)d_in[1];
    const int*   edst = (const int*)d_in[2];
    const float* ew   = (const float*)d_in[3];
    const float* W    = (const float*)d_in[4];
    const float* b    = (const float*)d_in[5];
    float*       out  = (float*)d_out;

    int n_nodes = in_sizes[0] / D;
    int n_edges = in_sizes[1];

    static cudaStream_t s_side = nullptr;
    static cudaEvent_t s_fork = nullptr, s_join = nullptr;
    if (!s_side) {
        cudaStreamCreateWithFlags(&s_side, cudaStreamNonBlocking);
        cudaEventCreateWithFlags(&s_fork, cudaEventDisableTiming);
        cudaEventCreateWithFlags(&s_join, cudaEventDisableTiming);
    }

    // fork: GEMM concurrent with bucket build
    cudaEventRecord(s_fork, 0);
    cudaStreamWaitEvent(s_side, s_fork, 0);
    gcn_gemm_kernel<<<(n_nodes + TILE_R - 1) / TILE_R, 256, 0, s_side>>>(X, W, n_nodes);
    cudaEventRecord(s_join, s_side);

    // bucket build on main stream
    void* p_cnt = nullptr; void* p_novf = nullptr;
    cudaGetSymbolAddress(&p_cnt, g_cnt);
    cudaGetSymbolAddress(&p_novf, g_novf);
    cudaMemsetAsync(p_cnt, 0, n_nodes * sizeof(int));
    cudaMemsetAsync(p_novf, 0, sizeof(int));
    fill_kernel<<<(n_edges + 255) / 256, 256>>>(esrc, edst, ew, n_edges);

    // join: gather needs buckets + support
    cudaStreamWaitEvent(0, s_join, 0);
    gather_kernel<<<(n_nodes * 32 + 255) / 256, 256>>>(b, out, n_nodes);
    ovf_kernel<<<4, 256>>>(out);
}